// round 10
// baseline (speedup 1.0000x reference)
#include <cuda_runtime.h>
#include <cuda_bf16.h>
#include <math.h>

// ---------------------------------------------------------------------------
// Problem constants
// ---------------------------------------------------------------------------
#define BB   8
#define TT   1500
#define TSD  750          // T / DS
#define DD   512
#define FFD  2048
#define HH   8
#define HDD  64
#define CBN  1025
#define CDD  64
#define QKVW (3*DD)          // 1536
#define MROWS_DS  (BB*TSD)   // 6000
#define MROWS     (BB*TT)    // 12000
#define COMMIT_N  (MROWS_DS*CDD)   // 384000

// ---------------------------------------------------------------------------
// Scratch (static device globals; no runtime allocation)
// ---------------------------------------------------------------------------
__device__ float g_x    [MROWS_DS*DD];
__device__ float g_ln   [MROWS*DD];
__device__ float g_ff   [(size_t)MROWS*FFD];
__device__ float g_xq   [MROWS_DS*CDD];
__device__ int   g_idx  [MROWS_DS];
__device__ float g_cbn  [CBN];
__device__ float g_pcb  [CBN*DD];          // codebook @ proj_out_w + b
__device__ float g_xfull[MROWS*DD];
__device__ float g_wqkv [DD*QKVW];         // packed [wq|wk|wv]
__device__ float g_bqkv [QKVW];
__device__ float g_qkv  [(size_t)MROWS*QKVW];
__device__ float g_ob   [MROWS*DD];
__device__ unsigned char g_mask[MROWS];
__device__ int   g_masktype;               // 0=u8, 1=i32, 2=f32
__device__ float g_crow [MROWS_DS];        // per-row commit-loss partial sums

// ---------------------------------------------------------------------------
// Helpers
// ---------------------------------------------------------------------------
// tanh via MUFU exp: tanh(z) = 1 - 2/(exp(2z)+1).  Stable at both tails.
__device__ __forceinline__ float gelu_tanh(float x) {
    float z = 0.7978845608028654f * (x + 0.044715f * x * x * x);
    float t = 1.0f - 2.0f / (__expf(2.0f * z) + 1.0f);
    return 0.5f * x * (1.0f + t);
}

// ---------------------------------------------------------------------------
// Mask dtype detection + canonicalization.
//   float32 true  -> word 0x3F800000
//   uint8 packed  -> words with multi-byte patterns (not 0 or 1)
//   int32         -> every word is 0 or 1
// Scan only MROWS/4 words (== 12000 bytes) so the uint8 case stays in bounds.
// ---------------------------------------------------------------------------
__global__ void maskdetect_k(const unsigned int* __restrict__ m) {
    __shared__ int fl[2];
    if (threadIdx.x < 2) fl[threadIdx.x] = 0;
    __syncthreads();
    for (int i = threadIdx.x; i < MROWS / 4; i += blockDim.x) {
        unsigned int w = m[i];
        if (w == 0x3F800000u)          atomicOr(&fl[1], 1);
        else if (w != 0u && w != 1u)   atomicOr(&fl[0], 1);
    }
    __syncthreads();
    if (threadIdx.x == 0)
        g_masktype = fl[1] ? 2 : (fl[0] ? 0 : 1);
}

__global__ void maskconv_k(const void* __restrict__ m) {
    int i = blockIdx.x * blockDim.x + threadIdx.x;
    if (i >= MROWS) return;
    int t = g_masktype;
    unsigned char v;
    if (t == 0)      v = ((const unsigned char*)m)[i] != 0;
    else if (t == 1) v = ((const int*)m)[i]           != 0;
    else             v = ((const float*)m)[i]         != 0.0f;
    g_mask[i] = v;
}

// x = embs[:, ::2]  (float4: 128 quads per row of 512)
__global__ void ds_k(const float* __restrict__ embs, float* __restrict__ x) {
    int i = blockIdx.x * blockDim.x + threadIdx.x;   // quad index
    if (i >= MROWS_DS * (DD / 4)) return;
    int d4 = i & (DD / 4 - 1);                       // 0..127
    int r  = i >> 7;
    int b = r / TSD, t = r % TSD;
    const float4* src = (const float4*)(embs + ((size_t)(b * TT + 2 * t)) * DD);
    ((float4*)(x + (size_t)r * DD))[d4] = src[d4];
}

// Pack [wq|wk|wv] and biases into one [K=512, N=1536] weight matrix.
__global__ void qkvcat_k(const float* __restrict__ wq, const float* __restrict__ wk,
                         const float* __restrict__ wv, const float* __restrict__ bq,
                         const float* __restrict__ bk, const float* __restrict__ bv) {
    int i = blockIdx.x * blockDim.x + threadIdx.x;
    if (i < DD * DD) {
        int k = i >> 9, n = i & (DD - 1);
        size_t row = (size_t)k * QKVW;
        g_wqkv[row + n]          = wq[i];
        g_wqkv[row + DD + n]     = wk[i];
        g_wqkv[row + 2 * DD + n] = wv[i];
    }
    if (i < DD) {
        g_bqkv[i]          = bq[i];
        g_bqkv[DD + i]     = bk[i];
        g_bqkv[2 * DD + i] = bv[i];
    }
}

// ---------------------------------------------------------------------------
// Row LayerNorm over D=512; 256 threads, warp-shuffle reduction.
// ---------------------------------------------------------------------------
__global__ __launch_bounds__(256)
void ln_k(const float* __restrict__ in, float* __restrict__ out,
          const float* __restrict__ g, const float* __restrict__ b) {
    __shared__ float wred[8];
    int r = blockIdx.x;
    int tid = threadIdx.x;
    int lane = tid & 31, wid = tid >> 5;
    const float* x = in + (size_t)r * DD;
    float v0 = x[tid], v1 = x[tid + 256];

    float s = v0 + v1;
    #pragma unroll
    for (int o = 16; o > 0; o >>= 1) s += __shfl_xor_sync(0xffffffffu, s, o);
    if (lane == 0) wred[wid] = s;
    __syncthreads();
    float mean = 0.f;
    #pragma unroll
    for (int i = 0; i < 8; i++) mean += wred[i];
    mean *= (1.0f / DD);
    __syncthreads();

    float d0 = v0 - mean, d1 = v1 - mean;
    float q = d0 * d0 + d1 * d1;
    #pragma unroll
    for (int o = 16; o > 0; o >>= 1) q += __shfl_xor_sync(0xffffffffu, q, o);
    if (lane == 0) wred[wid] = q;
    __syncthreads();
    float var = 0.f;
    #pragma unroll
    for (int i = 0; i < 8; i++) var += wred[i];
    float inv = rsqrtf(var * (1.0f / DD) + 1e-5f);

    float* y = out + (size_t)r * DD;
    y[tid]       = d0 * inv * g[tid]       + b[tid];
    y[tid + 256] = d1 * inv * g[tid + 256] + b[tid + 256];
}

// ---------------------------------------------------------------------------
// SGEMM: C[M,N] = epilogue(A[M,K] @ W[K,N] + bias [+ res])
// BM=BN=128, BK=16, 256 threads, 8x8/thread, double-buffered smem,
// register-staged global prefetch (2 float4 per array per thread),
// LDS.128 fragment loads. Requires K % 16 == 0 and N % 4 == 0.
// ---------------------------------------------------------------------------
#define BM 128
#define BN 128
#define BKK 16

template<bool GELU, bool RES>
__global__ __launch_bounds__(256)
void sgemm_k(const float* __restrict__ A, const float* __restrict__ W,
             const float* __restrict__ bias, const float* __restrict__ res,
             float* __restrict__ C, int M, int N, int K) {
    __shared__ float As[2][BKK][BM];
    __shared__ float Ws[2][BKK][BN];

    int tid = threadIdx.x;
    int tx = tid & 15, ty = tid >> 4;
    int bm = blockIdx.y * BM;
    int bn = blockIdx.x * BN;

    float acc[8][8];
    #pragma unroll
    for (int i = 0; i < 8; i++)
        #pragma unroll
        for (int j = 0; j < 8; j++) acc[i][j] = 0.0f;

    int aRow = tid >> 1;
    int aCol = (tid & 1) * 8;
    int wRow = tid >> 4;
    int wCol = (tid & 15) * 8;

    bool aValid  = (bm + aRow) < M;
    bool wValid0 = (bn + wCol) < N;       // N % 4 == 0 -> full float4 in range
    bool wValid1 = (bn + wCol + 4) < N;
    const float* Ap = A + (size_t)(bm + aRow) * K + aCol;
    const float* Wp = W + (size_t)wRow * N + bn + wCol;

    const float4 z4 = make_float4(0.f, 0.f, 0.f, 0.f);

    // initial tile -> buffer 0
    {
        float4 a0 = aValid  ? *(const float4*)(Ap)     : z4;
        float4 a1 = aValid  ? *(const float4*)(Ap + 4) : z4;
        float4 w0 = wValid0 ? *(const float4*)(Wp)     : z4;
        float4 w1 = wValid1 ? *(const float4*)(Wp + 4) : z4;
        As[0][aCol + 0][aRow] = a0.x;  As[0][aCol + 1][aRow] = a0.y;
        As[0][aCol + 2][aRow] = a0.z;  As[0][aCol + 3][aRow] = a0.w;
        As[0][aCol + 4][aRow] = a1.x;  As[0][aCol + 5][aRow] = a1.y;
        As[0][aCol + 6][aRow] = a1.z;  As[0][aCol + 7][aRow] = a1.w;
        *(float4*)&Ws[0][wRow][wCol]     = w0;
        *(float4*)&Ws[0][wRow][wCol + 4] = w1;
    }
    __syncthreads();

    int buf = 0;
    for (int k0 = 0; k0 < K; k0 += BKK) {
        bool has_next = (k0 + BKK) < K;
        float4 na0 = z4, na1 = z4, nw0 = z4, nw1 = z4;
        if (has_next) {
            if (aValid) {
                na0 = *(const float4*)(Ap + k0 + BKK);
                na1 = *(const float4*)(Ap + k0 + BKK + 4);
            }
            if (wValid0) nw0 = *(const float4*)(Wp + (size_t)(k0 + BKK) * N);
            if (wValid1) nw1 = *(const float4*)(Wp + (size_t)(k0 + BKK) * N + 4);
        }

        #pragma unroll
        for (int kk = 0; kk < BKK; kk++) {
            float4 a0 = *(const float4*)&As[buf][kk][ty * 4];
            float4 a1 = *(const float4*)&As[buf][kk][64 + ty * 4];
            float4 b0 = *(const float4*)&Ws[buf][kk][tx * 4];
            float4 b1 = *(const float4*)&Ws[buf][kk][64 + tx * 4];
            float ra[8] = {a0.x, a0.y, a0.z, a0.w, a1.x, a1.y, a1.z, a1.w};
            float rb[8] = {b0.x, b0.y, b0.z, b0.w, b1.x, b1.y, b1.z, b1.w};
            #pragma unroll
            for (int i = 0; i < 8; i++)
                #pragma unroll
                for (int j = 0; j < 8; j++)
                    acc[i][j] += ra[i] * rb[j];
        }

        if (has_next) {
            int nb = buf ^ 1;
            As[nb][aCol + 0][aRow] = na0.x;  As[nb][aCol + 1][aRow] = na0.y;
            As[nb][aCol + 2][aRow] = na0.z;  As[nb][aCol + 3][aRow] = na0.w;
            As[nb][aCol + 4][aRow] = na1.x;  As[nb][aCol + 5][aRow] = na1.y;
            As[nb][aCol + 6][aRow] = na1.z;  As[nb][aCol + 7][aRow] = na1.w;
            *(float4*)&Ws[nb][wRow][wCol]     = nw0;
            *(float4*)&Ws[nb][wRow][wCol + 4] = nw1;
            __syncthreads();
            buf = nb;
        }
    }

    #pragma unroll
    for (int i = 0; i < 8; i++) {
        int rloc = (i < 4) ? (ty * 4 + i) : (64 + ty * 4 + i - 4);
        int r = bm + rloc;
        if (r >= M) continue;
        #pragma unroll
        for (int j = 0; j < 8; j++) {
            int cloc = (j < 4) ? (tx * 4 + j) : (64 + tx * 4 + j - 4);
            int c = bn + cloc;
            if (c >= N) continue;
            float v = acc[i][j] + bias[c];
            if (GELU) v = gelu_tanh(v);
            if (RES)  v += res[(size_t)r * N + c];
            C[(size_t)r * N + c] = v;
        }
    }
}

// ---------------------------------------------------------------------------
// Codebook squared norms
// ---------------------------------------------------------------------------
__global__ void cbn_k(const float* __restrict__ cb) {
    int j = blockIdx.x * blockDim.x + threadIdx.x;
    if (j >= CBN) return;
    const float* c = cb + (size_t)j * CDD;
    float s = 0.f;
    #pragma unroll
    for (int d = 0; d < CDD; d++) s += c[d] * c[d];
    g_cbn[j] = s;
}

// ---------------------------------------------------------------------------
// VQ argmin (first-min tie-break) + per-row commit-loss partial sum.
// One block (128 threads) per row. Fully deterministic (no atomics).
// ---------------------------------------------------------------------------
__global__ __launch_bounds__(128)
void vq_k(const float* __restrict__ xq, const float* __restrict__ cb) {
    __shared__ float qs[CDD];
    __shared__ float sd[128];
    __shared__ int   si[128];

    int r = blockIdx.x;
    int tid = threadIdx.x;

    if (tid < CDD) qs[tid] = xq[(size_t)r * CDD + tid];
    __syncthreads();

    // ||xq||^2
    sd[tid] = (tid < CDD) ? qs[tid] * qs[tid] : 0.f;
    __syncthreads();
    for (int o = 64; o > 0; o >>= 1) {
        if (tid < o) sd[tid] += sd[tid + o];
        __syncthreads();
    }
    float xqn = sd[0];
    __syncthreads();

    float best = 3.4e38f;
    int bidx = 0;
    for (int j = tid; j < CBN; j += 128) {
        const float* c = cb + (size_t)j * CDD;
        float dot = 0.f;
        #pragma unroll
        for (int d = 0; d < CDD; d++) dot += qs[d] * c[d];
        float dist = xqn - 2.0f * dot + g_cbn[j];
        if (dist < best) { best = dist; bidx = j; }
    }
    sd[tid] = best; si[tid] = bidx;
    __syncthreads();
    for (int o = 64; o > 0; o >>= 1) {
        if (tid < o) {
            float d2 = sd[tid + o]; int i2 = si[tid + o];
            if (d2 < sd[tid] || (d2 == sd[tid] && i2 < si[tid])) {
                sd[tid] = d2; si[tid] = i2;
            }
        }
        __syncthreads();
    }
    int w = si[0];
    if (tid == 0) g_idx[r] = w;
    __syncthreads();

    // commit loss contribution: sum (cb[w] - xq)^2 -> per-row slot
    float cl = 0.f;
    if (tid < CDD) {
        float diff = cb[(size_t)w * CDD + tid] - qs[tid];
        cl = diff * diff;
    }
    sd[tid] = cl;
    __syncthreads();
    for (int o = 64; o > 0; o >>= 1) {
        if (tid < o) sd[tid] += sd[tid + o];
        __syncthreads();
    }
    if (tid == 0) g_crow[r] = sd[0];
}

// ---------------------------------------------------------------------------
// Gather precomputed P = codebook @ proj_out_w + b, apply repeat/mask/pos.
// float4: one quad per thread; mask/idx lookup amortized over 4 columns.
// ---------------------------------------------------------------------------
__global__ void gather_k(const float* __restrict__ P,
                         const float* __restrict__ pos,
                         float* __restrict__ out) {
    int i = blockIdx.x * blockDim.x + threadIdx.x;   // quad index
    if (i >= MROWS * (DD / 4)) return;
    int d4 = i & (DD / 4 - 1);                       // 0..127
    int bt = i >> 7;
    int b = bt / TT, t = bt % TT;
    int sel = g_mask[bt] ? g_idx[b * TSD + (t >> 1)] : (CBN - 1);
    float4 pv = ((const float4*)(P   + (size_t)sel * DD))[d4];
    float4 ev = ((const float4*)(pos + (size_t)t   * DD))[d4];
    float4 r;
    r.x = pv.x + ev.x;  r.y = pv.y + ev.y;
    r.z = pv.z + ev.z;  r.w = pv.w + ev.w;
    ((float4*)(out + (size_t)bt * DD))[d4] = r;
}

// ---------------------------------------------------------------------------
// Flash attention over the packed QKV buffer [MROWS, 1536]:
//   Q at col h*64, K at col 512 + h*64, V at col 1024 + h*64.
// grid (ceil(T/128), H, B), 128 threads; one query/thread. 64-key tiles,
// 32-key two-pass softmax chunks (one o-rescale per chunk). All global
// accesses are 128-bit. QK_SCALE == 1.
// ---------------------------------------------------------------------------
#define AQB 128

__global__ __launch_bounds__(AQB)
void attn_k(const float* __restrict__ QKV, float* __restrict__ O) {
    __shared__ float Ks[64][HDD];
    __shared__ float Vs[64][HDD];
    __shared__ float Ss[32][AQB];

    int h = blockIdx.y, b = blockIdx.z;
    int tid = threadIdx.x;
    int qi = blockIdx.x * AQB + tid;
    bool valid = qi < TT;

    float q[HDD];
    if (valid) {
        const float4* qp = (const float4*)(QKV + ((size_t)(b * TT + qi)) * QKVW
                                               + h * HDD);
        #pragma unroll
        for (int d4 = 0; d4 < HDD / 4; d4++) {
            float4 v = qp[d4];
            q[d4 * 4 + 0] = v.x; q[d4 * 4 + 1] = v.y;
            q[d4 * 4 + 2] = v.z; q[d4 * 4 + 3] = v.w;
        }
    }

    float m = -1e30f, l = 0.f;
    float o[HDD];
    #pragma unroll
    for (int d = 0; d < HDD; d++) o[d] = 0.f;

    const float4 z4 = make_float4(0.f, 0.f, 0.f, 0.f);

    for (int kb = 0; kb < TT; kb += 64) {
        // stage 64x64 K and V tiles: 1024 float4 each, 8 per thread
        #pragma unroll
        for (int i = 0; i < 8; i++) {
            int e   = tid + i * AQB;       // 0..1023
            int row = e >> 4;              // 16 float4 per row
            int c4  = (e & 15) * 4;
            int kt  = kb + row;
            float4 kv = z4, vv = z4;
            if (kt < TT) {
                size_t base = ((size_t)(b * TT + kt)) * QKVW + h * HDD + c4;
                kv = *(const float4*)(QKV + base + DD);       // K block
                vv = *(const float4*)(QKV + base + 2 * DD);   // V block
            }
            *(float4*)&Ks[row][c4] = kv;
            *(float4*)&Vs[row][c4] = vv;
        }
        __syncthreads();

        int nk = min(64, TT - kb);
        if (valid) {
            #pragma unroll
            for (int c = 0; c < 2; c++) {
                int jb = c * 32;
                if (jb >= nk) break;
                int jn = min(32, nk - jb);

                // pass 1: scores + chunk max
                float tm = -1e30f;
                for (int j = 0; j < jn; j++) {
                    float s = 0.f;
                    #pragma unroll
                    for (int d = 0; d < HDD; d++) s += q[d] * Ks[jb + j][d];
                    Ss[j][tid] = s;
                    tm = fmaxf(tm, s);
                }

                // single rescale
                float nm = fmaxf(m, tm);
                float sc = __expf(m - nm);
                l *= sc;
                #pragma unroll
                for (int d = 0; d < HDD; d++) o[d] *= sc;

                // pass 2: exp + PV accumulate
                for (int j = 0; j < jn; j++) {
                    float p = __expf(Ss[j][tid] - nm);
                    l += p;
                    #pragma unroll
                    for (int d = 0; d < HDD; d++) o[d] += p * Vs[jb + j][d];
                }
                m = nm;
            }
        }
        __syncthreads();
    }

    if (valid) {
        float invl = 1.0f / l;
        float4* op = (float4*)(O + ((size_t)(b * TT + qi)) * DD + h * HDD);
        #pragma unroll
        for (int d4 = 0; d4 < HDD / 4; d4++) {
            float4 v;
            v.x = o[d4 * 4 + 0] * invl;
            v.y = o[d4 * 4 + 1] * invl;
            v.z = o[d4 * 4 + 2] * invl;
            v.w = o[d4 * 4 + 3] * invl;
            op[d4] = v;
        }
    }
}

// ---------------------------------------------------------------------------
// Deterministic commit-loss reduction: single block, fixed summation order.
// Bit-identical on every replay.
// ---------------------------------------------------------------------------
__global__ __launch_bounds__(256)
void fin_k(float* __restrict__ out, int pos) {
    __shared__ float red[256];
    int tid = threadIdx.x;
    float s = 0.f;
    for (int r = tid; r < MROWS_DS; r += 256) s += g_crow[r];
    red[tid] = s;
    __syncthreads();
    for (int o = 128; o > 0; o >>= 1) {
        if (tid < o) red[tid] += red[tid + o];
        __syncthreads();
    }
    if (tid == 0) out[pos] = red[0] * (1.0f / (float)COMMIT_N);
}

// ---------------------------------------------------------------------------
// Launch
// ---------------------------------------------------------------------------
static float* sym(const void* s) {
    void* p = nullptr;
    cudaGetSymbolAddress(&p, s);
    return (float*)p;
}

extern "C" void kernel_launch(void* const* d_in, const int* in_sizes, int n_in,
                              void* d_out, int out_size) {
    const float* embs      = (const float*)d_in[0];
    const void*  maskraw   = d_in[1];
    const float* mlp_ln_g  = (const float*)d_in[2];
    const float* mlp_ln_b  = (const float*)d_in[3];
    const float* mlp_w1    = (const float*)d_in[4];
    const float* mlp_b1    = (const float*)d_in[5];
    const float* mlp_w2    = (const float*)d_in[6];
    const float* mlp_b2    = (const float*)d_in[7];
    const float* proj_in_w = (const float*)d_in[8];
    const float* proj_in_b = (const float*)d_in[9];
    const float* codebook  = (const float*)d_in[10];
    const float* proj_out_w= (const float*)d_in[11];
    const float* proj_out_b= (const float*)d_in[12];
    const float* pos_emb   = (const float*)d_in[13];
    const float* attn_ln_g = (const float*)d_in[14];
    const float* attn_ln_b = (const float*)d_in[15];
    const float* wq        = (const float*)d_in[16];
    const float* bq        = (const float*)d_in[17];
    const float* wk        = (const float*)d_in[18];
    const float* bk        = (const float*)d_in[19];
    const float* wv        = (const float*)d_in[20];
    const float* bv        = (const float*)d_in[21];
    const float* wo        = (const float*)d_in[22];
    const float* bo        = (const float*)d_in[23];
    const float* ffn_ln_g  = (const float*)d_in[24];
    const float* ffn_ln_b  = (const float*)d_in[25];
    const float* ffn_w1    = (const float*)d_in[26];
    const float* ffn_b1    = (const float*)d_in[27];
    const float* ffn_w2    = (const float*)d_in[28];
    const float* ffn_b2    = (const float*)d_in[29];
    const float* ln_post_g = (const float*)d_in[30];
    const float* ln_post_b = (const float*)d_in[31];

    float* out = (float*)d_out;

    float* px     = sym(g_x);
    float* pln    = sym(g_ln);
    float* pff    = sym(g_ff);
    float* pxq    = sym(g_xq);
    float* ppcb   = sym(g_pcb);
    float* pxfull = sym(g_xfull);
    float* pwqkv  = sym(g_wqkv);
    float* pbqkv  = sym(g_bqkv);
    float* pqkv   = sym(g_qkv);
    float* po     = sym(g_ob);

    maskdetect_k<<<1, 256>>>((const unsigned int*)maskraw);
    maskconv_k<<<(MROWS + 255) / 256, 256>>>(maskraw);

    // x = embs[:, ::2]
    ds_k<<<(MROWS_DS * (DD / 4) + 255) / 256, 256>>>(embs, px);

    // pack QKV weights; codebook norms + precomputed proj_out of codebook
    qkvcat_k<<<(DD * DD + 255) / 256, 256>>>(wq, wk, wv, bq, bk, bv);
    cbn_k<<<(CBN + 255) / 256, 256>>>(codebook);
    {
        dim3 g((DD + BN - 1) / BN, (CBN + BM - 1) / BM);
        sgemm_k<false, false><<<g, 256>>>(codebook, proj_out_w, proj_out_b,
                                          nullptr, ppcb, CBN, DD, CDD);
    }

    // MLP block
    ln_k<<<MROWS_DS, 256>>>(px, pln, mlp_ln_g, mlp_ln_b);
    {
        dim3 g1((FFD + BN - 1) / BN, (MROWS_DS + BM - 1) / BM);
        sgemm_k<true, false><<<g1, 256>>>(pln, mlp_w1, mlp_b1, nullptr, pff,
                                          MROWS_DS, FFD, DD);
        dim3 g2((DD + BN - 1) / BN, (MROWS_DS + BM - 1) / BM);
        sgemm_k<false, true><<<g2, 256>>>(pff, mlp_w2, mlp_b2, px, px,
                                          MROWS_DS, DD, FFD);
    }

    // proj_in
    {
        dim3 g((CDD + BN - 1) / BN, (MROWS_DS + BM - 1) / BM);
        sgemm_k<false, false><<<g, 256>>>(px, proj_in_w, proj_in_b, nullptr, pxq,
                                          MROWS_DS, CDD, DD);
    }

    // VQ
    vq_k<<<MROWS_DS, 128>>>(pxq, codebook);

    // gather P[sel] + pos_emb  (repeat + mask fused)
    gather_k<<<(MROWS * (DD / 4) + 255) / 256, 256>>>(ppcb, pos_emb, pxfull);

    // Attention block: fused QKV GEMM (N=1536 -> 1128 CTAs, good wave shape)
    ln_k<<<MROWS, 256>>>(pxfull, pln, attn_ln_g, attn_ln_b);
    {
        dim3 g((QKVW + BN - 1) / BN, (MROWS + BM - 1) / BM);
        sgemm_k<false, false><<<g, 256>>>(pln, pwqkv, pbqkv, nullptr, pqkv,
                                          MROWS, QKVW, DD);
    }
    {
        dim3 g((TT + AQB - 1) / AQB, HH, BB);
        attn_k<<<g, AQB>>>(pqkv, po);
    }
    {
        dim3 g((DD + BN - 1) / BN, (MROWS + BM - 1) / BM);
        sgemm_k<false, true><<<g, 256>>>(po, wo, bo, pxfull, pxfull, MROWS, DD, DD);
    }

    // FFN block
    ln_k<<<MROWS, 256>>>(pxfull, pln, ffn_ln_g, ffn_ln_b);
    {
        dim3 g1((FFD + BN - 1) / BN, (MROWS + BM - 1) / BM);
        sgemm_k<true, false><<<g1, 256>>>(pln, ffn_w1, ffn_b1, nullptr, pff,
                                          MROWS, FFD, DD);
        dim3 g2((DD + BN - 1) / BN, (MROWS + BM - 1) / BM);
        sgemm_k<false, true><<<g2, 256>>>(pff, ffn_w2, ffn_b2, pxfull, pxfull,
                                          MROWS, DD, FFD);
    }

    // final LN straight into d_out; commit loss in the last slot
    ln_k<<<MROWS, 256>>>(pxfull, out, ln_post_g, ln_post_b);
    fin_k<<<1, 256>>>(out, out_size - 1);
}

// round 12
// speedup vs baseline: 1.2126x; 1.2126x over previous
#include <cuda_runtime.h>
#include <cuda_bf16.h>
#include <math.h>

// ---------------------------------------------------------------------------
// Problem constants
// ---------------------------------------------------------------------------
#define BB   8
#define TT   1500
#define TSD  750          // T / DS
#define DD   512
#define FFD  2048
#define HH   8
#define HDD  64
#define CBN  1025
#define CDD  64
#define QKVW (3*DD)          // 1536
#define MROWS_DS  (BB*TSD)   // 6000
#define MROWS     (BB*TT)    // 12000
#define COMMIT_N  (MROWS_DS*CDD)   // 384000

// ---------------------------------------------------------------------------
// Scratch (static device globals; no runtime allocation)
// ---------------------------------------------------------------------------
__device__ float g_x    [MROWS_DS*DD];
__device__ float g_ln   [MROWS*DD];
__device__ float g_ff   [(size_t)MROWS*FFD];
__device__ float g_xq   [MROWS_DS*CDD];
__device__ int   g_idx  [MROWS_DS];
__device__ float g_cbn  [CBN];
__device__ float g_pcb  [CBN*DD];          // codebook @ proj_out_w + b
__device__ float g_xfull[MROWS*DD];
__device__ float g_wqkv [DD*QKVW];         // packed [wq|wk|wv]
__device__ float g_bqkv [QKVW];
__device__ float g_qkv  [(size_t)MROWS*QKVW];
__device__ float g_ob   [MROWS*DD];
__device__ unsigned char g_mask[MROWS];
__device__ int   g_masktype;               // 0=u8, 1=i32, 2=f32
__device__ float g_crow [MROWS_DS];        // per-row commit-loss partial sums

// ---------------------------------------------------------------------------
// Helpers
// ---------------------------------------------------------------------------
// tanh via MUFU exp: tanh(z) = 1 - 2/(exp(2z)+1).  Stable at both tails.
__device__ __forceinline__ float gelu_tanh(float x) {
    float z = 0.7978845608028654f * (x + 0.044715f * x * x * x);
    float t = 1.0f - 2.0f / (__expf(2.0f * z) + 1.0f);
    return 0.5f * x * (1.0f + t);
}

// Round fp32 -> tf32 (rna, matching cuBLAS tf32 mode).
__device__ __forceinline__ float tf32r(float x) {
    unsigned u;
    asm("cvt.rna.tf32.f32 %0, %1;" : "=r"(u) : "f"(x));
    return __uint_as_float(u);
}

// ---------------------------------------------------------------------------
// Mask dtype detection + canonicalization (u8 / i32 / f32).
// ---------------------------------------------------------------------------
__global__ void maskdetect_k(const unsigned int* __restrict__ m) {
    __shared__ int fl[2];
    if (threadIdx.x < 2) fl[threadIdx.x] = 0;
    __syncthreads();
    for (int i = threadIdx.x; i < MROWS / 4; i += blockDim.x) {
        unsigned int w = m[i];
        if (w == 0x3F800000u)          atomicOr(&fl[1], 1);
        else if (w != 0u && w != 1u)   atomicOr(&fl[0], 1);
    }
    __syncthreads();
    if (threadIdx.x == 0)
        g_masktype = fl[1] ? 2 : (fl[0] ? 0 : 1);
}

__global__ void maskconv_k(const void* __restrict__ m) {
    int i = blockIdx.x * blockDim.x + threadIdx.x;
    if (i >= MROWS) return;
    int t = g_masktype;
    unsigned char v;
    if (t == 0)      v = ((const unsigned char*)m)[i] != 0;
    else if (t == 1) v = ((const int*)m)[i]           != 0;
    else             v = ((const float*)m)[i]         != 0.0f;
    g_mask[i] = v;
}

// x = embs[:, ::2]  (float4)
__global__ void ds_k(const float* __restrict__ embs, float* __restrict__ x) {
    int i = blockIdx.x * blockDim.x + threadIdx.x;
    if (i >= MROWS_DS * (DD / 4)) return;
    int d4 = i & (DD / 4 - 1);
    int r  = i >> 7;
    int b = r / TSD, t = r % TSD;
    const float4* src = (const float4*)(embs + ((size_t)(b * TT + 2 * t)) * DD);
    ((float4*)(x + (size_t)r * DD))[d4] = src[d4];
}

// Pack [wq|wk|wv] and biases into one [K=512, N=1536] weight matrix.
__global__ void qkvcat_k(const float* __restrict__ wq, const float* __restrict__ wk,
                         const float* __restrict__ wv, const float* __restrict__ bq,
                         const float* __restrict__ bk, const float* __restrict__ bv) {
    int i = blockIdx.x * blockDim.x + threadIdx.x;
    if (i < DD * DD) {
        int k = i >> 9, n = i & (DD - 1);
        size_t row = (size_t)k * QKVW;
        g_wqkv[row + n]          = wq[i];
        g_wqkv[row + DD + n]     = wk[i];
        g_wqkv[row + 2 * DD + n] = wv[i];
    }
    if (i < DD) {
        g_bqkv[i]          = bq[i];
        g_bqkv[DD + i]     = bk[i];
        g_bqkv[2 * DD + i] = bv[i];
    }
}

// ---------------------------------------------------------------------------
// Row LayerNorm over D=512; 256 threads, warp-shuffle reduction.
// ---------------------------------------------------------------------------
__global__ __launch_bounds__(256)
void ln_k(const float* __restrict__ in, float* __restrict__ out,
          const float* __restrict__ g, const float* __restrict__ b) {
    __shared__ float wred[8];
    int r = blockIdx.x;
    int tid = threadIdx.x;
    int lane = tid & 31, wid = tid >> 5;
    const float* x = in + (size_t)r * DD;
    float v0 = x[tid], v1 = x[tid + 256];

    float s = v0 + v1;
    #pragma unroll
    for (int o = 16; o > 0; o >>= 1) s += __shfl_xor_sync(0xffffffffu, s, o);
    if (lane == 0) wred[wid] = s;
    __syncthreads();
    float mean = 0.f;
    #pragma unroll
    for (int i = 0; i < 8; i++) mean += wred[i];
    mean *= (1.0f / DD);
    __syncthreads();

    float d0 = v0 - mean, d1 = v1 - mean;
    float q = d0 * d0 + d1 * d1;
    #pragma unroll
    for (int o = 16; o > 0; o >>= 1) q += __shfl_xor_sync(0xffffffffu, q, o);
    if (lane == 0) wred[wid] = q;
    __syncthreads();
    float var = 0.f;
    #pragma unroll
    for (int i = 0; i < 8; i++) var += wred[i];
    float inv = rsqrtf(var * (1.0f / DD) + 1e-5f);

    float* y = out + (size_t)r * DD;
    y[tid]       = d0 * inv * g[tid]       + b[tid];
    y[tid + 256] = d1 * inv * g[tid + 256] + b[tid + 256];
}

// ---------------------------------------------------------------------------
// fp32 SGEMM (exact; used UPSTREAM of the VQ argmin + tiny pcb GEMM).
// BM=BN=128, BK=16, 256 threads, 8x8/thread, double-buffered.
// ---------------------------------------------------------------------------
#define BM 128
#define BN 128
#define BKK 16

template<bool GELU, bool RES>
__global__ __launch_bounds__(256)
void sgemm_k(const float* __restrict__ A, const float* __restrict__ W,
             const float* __restrict__ bias, const float* __restrict__ res,
             float* __restrict__ C, int M, int N, int K) {
    __shared__ float As[2][BKK][BM];
    __shared__ float Ws[2][BKK][BN];

    int tid = threadIdx.x;
    int tx = tid & 15, ty = tid >> 4;
    int bm = blockIdx.y * BM;
    int bn = blockIdx.x * BN;

    float acc[8][8];
    #pragma unroll
    for (int i = 0; i < 8; i++)
        #pragma unroll
        for (int j = 0; j < 8; j++) acc[i][j] = 0.0f;

    int aRow = tid >> 1;
    int aCol = (tid & 1) * 8;
    int wRow = tid >> 4;
    int wCol = (tid & 15) * 8;

    bool aValid  = (bm + aRow) < M;
    bool wValid0 = (bn + wCol) < N;
    bool wValid1 = (bn + wCol + 4) < N;
    const float* Ap = A + (size_t)(bm + aRow) * K + aCol;
    const float* Wp = W + (size_t)wRow * N + bn + wCol;

    const float4 z4 = make_float4(0.f, 0.f, 0.f, 0.f);

    {
        float4 a0 = aValid  ? *(const float4*)(Ap)     : z4;
        float4 a1 = aValid  ? *(const float4*)(Ap + 4) : z4;
        float4 w0 = wValid0 ? *(const float4*)(Wp)     : z4;
        float4 w1 = wValid1 ? *(const float4*)(Wp + 4) : z4;
        As[0][aCol + 0][aRow] = a0.x;  As[0][aCol + 1][aRow] = a0.y;
        As[0][aCol + 2][aRow] = a0.z;  As[0][aCol + 3][aRow] = a0.w;
        As[0][aCol + 4][aRow] = a1.x;  As[0][aCol + 5][aRow] = a1.y;
        As[0][aCol + 6][aRow] = a1.z;  As[0][aCol + 7][aRow] = a1.w;
        *(float4*)&Ws[0][wRow][wCol]     = w0;
        *(float4*)&Ws[0][wRow][wCol + 4] = w1;
    }
    __syncthreads();

    int buf = 0;
    for (int k0 = 0; k0 < K; k0 += BKK) {
        bool has_next = (k0 + BKK) < K;
        float4 na0 = z4, na1 = z4, nw0 = z4, nw1 = z4;
        if (has_next) {
            if (aValid) {
                na0 = *(const float4*)(Ap + k0 + BKK);
                na1 = *(const float4*)(Ap + k0 + BKK + 4);
            }
            if (wValid0) nw0 = *(const float4*)(Wp + (size_t)(k0 + BKK) * N);
            if (wValid1) nw1 = *(const float4*)(Wp + (size_t)(k0 + BKK) * N + 4);
        }

        #pragma unroll
        for (int kk = 0; kk < BKK; kk++) {
            float4 a0 = *(const float4*)&As[buf][kk][ty * 4];
            float4 a1 = *(const float4*)&As[buf][kk][64 + ty * 4];
            float4 b0 = *(const float4*)&Ws[buf][kk][tx * 4];
            float4 b1 = *(const float4*)&Ws[buf][kk][64 + tx * 4];
            float ra[8] = {a0.x, a0.y, a0.z, a0.w, a1.x, a1.y, a1.z, a1.w};
            float rb[8] = {b0.x, b0.y, b0.z, b0.w, b1.x, b1.y, b1.z, b1.w};
            #pragma unroll
            for (int i = 0; i < 8; i++)
                #pragma unroll
                for (int j = 0; j < 8; j++)
                    acc[i][j] += ra[i] * rb[j];
        }

        if (has_next) {
            int nb = buf ^ 1;
            As[nb][aCol + 0][aRow] = na0.x;  As[nb][aCol + 1][aRow] = na0.y;
            As[nb][aCol + 2][aRow] = na0.z;  As[nb][aCol + 3][aRow] = na0.w;
            As[nb][aCol + 4][aRow] = na1.x;  As[nb][aCol + 5][aRow] = na1.y;
            As[nb][aCol + 6][aRow] = na1.z;  As[nb][aCol + 7][aRow] = na1.w;
            *(float4*)&Ws[nb][wRow][wCol]     = nw0;
            *(float4*)&Ws[nb][wRow][wCol + 4] = nw1;
            __syncthreads();
            buf = nb;
        }
    }

    #pragma unroll
    for (int i = 0; i < 8; i++) {
        int rloc = (i < 4) ? (ty * 4 + i) : (64 + ty * 4 + i - 4);
        int r = bm + rloc;
        if (r >= M) continue;
        #pragma unroll
        for (int j = 0; j < 8; j++) {
            int cloc = (j < 4) ? (tx * 4 + j) : (64 + tx * 4 + j - 4);
            int c = bn + cloc;
            if (c >= N) continue;
            float v = acc[i][j] + bias[c];
            if (GELU) v = gelu_tanh(v);
            if (RES)  v += res[(size_t)r * N + c];
            C[(size_t)r * N + c] = v;
        }
    }
}

// ---------------------------------------------------------------------------
// tf32 tensor-core GEMM (used DOWNSTREAM of the VQ argmin).
// BM=BN=128, BK=16, 256 threads = 8 warps (2x4). Warp tile 64x32 via
// m16n8k8 tf32 mma.sync (4x4 tiles, fp32 accumulate). Inputs rounded to
// tf32 once at smem-store (cvt.rna). Padded smem rows (136) make fragment
// LDS conflict-free. Requires K % 16 == 0 and N % 128 == 0.
// ---------------------------------------------------------------------------
#define TPAD 136

template<bool GELU, bool RES>
__global__ __launch_bounds__(256)
void tgemm_k(const float* __restrict__ A, const float* __restrict__ W,
             const float* __restrict__ bias, const float* __restrict__ res,
             float* __restrict__ C, int M, int N, int K) {
    __shared__ float As[2][BKK][TPAD];
    __shared__ float Ws[2][BKK][TPAD];

    int tid  = threadIdx.x;
    int lane = tid & 31;
    int g    = lane >> 2;          // 0..7
    int tig  = lane & 3;           // 0..3
    int warp = tid >> 5;
    int wm   = warp >> 2;          // 0..1
    int wn   = warp & 3;           // 0..3
    int bm = blockIdx.y * BM;
    int bn = blockIdx.x * BN;

    float acc[4][4][4];
    #pragma unroll
    for (int i = 0; i < 4; i++)
        #pragma unroll
        for (int j = 0; j < 4; j++)
            #pragma unroll
            for (int r = 0; r < 4; r++) acc[i][j][r] = 0.f;

    int aRow = tid >> 1;           // 0..127
    int aCol = (tid & 1) * 8;      // 0 or 8
    int wRow = tid >> 4;           // 0..15
    int wCol = (tid & 15) * 8;     // 0..120

    bool aValid = (bm + aRow) < M;
    const float* Ap = A + (size_t)(bm + aRow) * K + aCol;
    const float* Wp = W + (size_t)wRow * N + bn + wCol;

    const float4 z4 = make_float4(0.f, 0.f, 0.f, 0.f);

    // initial tile -> buffer 0 (tf32-round at store)
    {
        float4 a0 = aValid ? *(const float4*)(Ap)     : z4;
        float4 a1 = aValid ? *(const float4*)(Ap + 4) : z4;
        float4 w0 = *(const float4*)(Wp);
        float4 w1 = *(const float4*)(Wp + 4);
        As[0][aCol + 0][aRow] = tf32r(a0.x);  As[0][aCol + 1][aRow] = tf32r(a0.y);
        As[0][aCol + 2][aRow] = tf32r(a0.z);  As[0][aCol + 3][aRow] = tf32r(a0.w);
        As[0][aCol + 4][aRow] = tf32r(a1.x);  As[0][aCol + 5][aRow] = tf32r(a1.y);
        As[0][aCol + 6][aRow] = tf32r(a1.z);  As[0][aCol + 7][aRow] = tf32r(a1.w);
        Ws[0][wRow][wCol + 0] = tf32r(w0.x);  Ws[0][wRow][wCol + 1] = tf32r(w0.y);
        Ws[0][wRow][wCol + 2] = tf32r(w0.z);  Ws[0][wRow][wCol + 3] = tf32r(w0.w);
        Ws[0][wRow][wCol + 4] = tf32r(w1.x);  Ws[0][wRow][wCol + 5] = tf32r(w1.y);
        Ws[0][wRow][wCol + 6] = tf32r(w1.z);  Ws[0][wRow][wCol + 7] = tf32r(w1.w);
    }
    __syncthreads();

    int buf = 0;
    for (int k0 = 0; k0 < K; k0 += BKK) {
        bool has_next = (k0 + BKK) < K;
        float4 na0 = z4, na1 = z4, nw0 = z4, nw1 = z4;
        if (has_next) {
            if (aValid) {
                na0 = *(const float4*)(Ap + k0 + BKK);
                na1 = *(const float4*)(Ap + k0 + BKK + 4);
            }
            nw0 = *(const float4*)(Wp + (size_t)(k0 + BKK) * N);
            nw1 = *(const float4*)(Wp + (size_t)(k0 + BKK) * N + 4);
        }

        #pragma unroll
        for (int kk = 0; kk < BKK; kk += 8) {
            unsigned af[4][4], bf[4][2];
            #pragma unroll
            for (int mt = 0; mt < 4; mt++) {
                int m0 = wm * 64 + mt * 16 + g;
                af[mt][0] = __float_as_uint(As[buf][kk + tig    ][m0]);
                af[mt][1] = __float_as_uint(As[buf][kk + tig    ][m0 + 8]);
                af[mt][2] = __float_as_uint(As[buf][kk + tig + 4][m0]);
                af[mt][3] = __float_as_uint(As[buf][kk + tig + 4][m0 + 8]);
            }
            #pragma unroll
            for (int nt = 0; nt < 4; nt++) {
                int n0 = wn * 32 + nt * 8 + g;
                bf[nt][0] = __float_as_uint(Ws[buf][kk + tig    ][n0]);
                bf[nt][1] = __float_as_uint(Ws[buf][kk + tig + 4][n0]);
            }
            #pragma unroll
            for (int mt = 0; mt < 4; mt++)
                #pragma unroll
                for (int nt = 0; nt < 4; nt++)
                    asm volatile(
                        "mma.sync.aligned.m16n8k8.row.col.f32.tf32.tf32.f32 "
                        "{%0,%1,%2,%3}, {%4,%5,%6,%7}, {%8,%9}, {%0,%1,%2,%3};"
                        : "+f"(acc[mt][nt][0]), "+f"(acc[mt][nt][1]),
                          "+f"(acc[mt][nt][2]), "+f"(acc[mt][nt][3])
                        : "r"(af[mt][0]), "r"(af[mt][1]),
                          "r"(af[mt][2]), "r"(af[mt][3]),
                          "r"(bf[nt][0]), "r"(bf[nt][1]));
        }

        if (has_next) {
            int nb = buf ^ 1;
            As[nb][aCol + 0][aRow] = tf32r(na0.x);  As[nb][aCol + 1][aRow] = tf32r(na0.y);
            As[nb][aCol + 2][aRow] = tf32r(na0.z);  As[nb][aCol + 3][aRow] = tf32r(na0.w);
            As[nb][aCol + 4][aRow] = tf32r(na1.x);  As[nb][aCol + 5][aRow] = tf32r(na1.y);
            As[nb][aCol + 6][aRow] = tf32r(na1.z);  As[nb][aCol + 7][aRow] = tf32r(na1.w);
            Ws[nb][wRow][wCol + 0] = tf32r(nw0.x);  Ws[nb][wRow][wCol + 1] = tf32r(nw0.y);
            Ws[nb][wRow][wCol + 2] = tf32r(nw0.z);  Ws[nb][wRow][wCol + 3] = tf32r(nw0.w);
            Ws[nb][wRow][wCol + 4] = tf32r(nw1.x);  Ws[nb][wRow][wCol + 5] = tf32r(nw1.y);
            Ws[nb][wRow][wCol + 6] = tf32r(nw1.z);  Ws[nb][wRow][wCol + 7] = tf32r(nw1.w);
            __syncthreads();
            buf = nb;
        }
    }

    // epilogue: c0/c1 at row g, cols 2tig/2tig+1; c2/c3 at row g+8.
    #pragma unroll
    for (int mt = 0; mt < 4; mt++) {
        int r0 = bm + wm * 64 + mt * 16 + g;
        int r1 = r0 + 8;
        #pragma unroll
        for (int nt = 0; nt < 4; nt++) {
            int cc = bn + wn * 32 + nt * 8 + 2 * tig;
            float bb0 = bias[cc], bb1 = bias[cc + 1];
            if (r0 < M) {
                float v0 = acc[mt][nt][0] + bb0;
                float v1 = acc[mt][nt][1] + bb1;
                if (GELU) { v0 = gelu_tanh(v0); v1 = gelu_tanh(v1); }
                if (RES) {
                    float2 rv = *(const float2*)(res + (size_t)r0 * N + cc);
                    v0 += rv.x; v1 += rv.y;
                }
                float2 o; o.x = v0; o.y = v1;
                *(float2*)(C + (size_t)r0 * N + cc) = o;
            }
            if (r1 < M) {
                float v2 = acc[mt][nt][2] + bb0;
                float v3 = acc[mt][nt][3] + bb1;
                if (GELU) { v2 = gelu_tanh(v2); v3 = gelu_tanh(v3); }
                if (RES) {
                    float2 rv = *(const float2*)(res + (size_t)r1 * N + cc);
                    v2 += rv.x; v3 += rv.y;
                }
                float2 o; o.x = v2; o.y = v3;
                *(float2*)(C + (size_t)r1 * N + cc) = o;
            }
        }
    }
}

// ---------------------------------------------------------------------------
// Codebook squared norms
// ---------------------------------------------------------------------------
__global__ void cbn_k(const float* __restrict__ cb) {
    int j = blockIdx.x * blockDim.x + threadIdx.x;
    if (j >= CBN) return;
    const float* c = cb + (size_t)j * CDD;
    float s = 0.f;
    #pragma unroll
    for (int d = 0; d < CDD; d++) s += c[d] * c[d];
    g_cbn[j] = s;
}

// ---------------------------------------------------------------------------
// VQ argmin (first-min tie-break) + per-row commit-loss partial sum.
// One block (128 threads) per row. Fully deterministic (no atomics).
// ---------------------------------------------------------------------------
__global__ __launch_bounds__(128)
void vq_k(const float* __restrict__ xq, const float* __restrict__ cb) {
    __shared__ float qs[CDD];
    __shared__ float sd[128];
    __shared__ int   si[128];

    int r = blockIdx.x;
    int tid = threadIdx.x;

    if (tid < CDD) qs[tid] = xq[(size_t)r * CDD + tid];
    __syncthreads();

    sd[tid] = (tid < CDD) ? qs[tid] * qs[tid] : 0.f;
    __syncthreads();
    for (int o = 64; o > 0; o >>= 1) {
        if (tid < o) sd[tid] += sd[tid + o];
        __syncthreads();
    }
    float xqn = sd[0];
    __syncthreads();

    float best = 3.4e38f;
    int bidx = 0;
    for (int j = tid; j < CBN; j += 128) {
        const float* c = cb + (size_t)j * CDD;
        float dot = 0.f;
        #pragma unroll
        for (int d = 0; d < CDD; d++) dot += qs[d] * c[d];
        float dist = xqn - 2.0f * dot + g_cbn[j];
        if (dist < best) { best = dist; bidx = j; }
    }
    sd[tid] = best; si[tid] = bidx;
    __syncthreads();
    for (int o = 64; o > 0; o >>= 1) {
        if (tid < o) {
            float d2 = sd[tid + o]; int i2 = si[tid + o];
            if (d2 < sd[tid] || (d2 == sd[tid] && i2 < si[tid])) {
                sd[tid] = d2; si[tid] = i2;
            }
        }
        __syncthreads();
    }
    int w = si[0];
    if (tid == 0) g_idx[r] = w;
    __syncthreads();

    float cl = 0.f;
    if (tid < CDD) {
        float diff = cb[(size_t)w * CDD + tid] - qs[tid];
        cl = diff * diff;
    }
    sd[tid] = cl;
    __syncthreads();
    for (int o = 64; o > 0; o >>= 1) {
        if (tid < o) sd[tid] += sd[tid + o];
        __syncthreads();
    }
    if (tid == 0) g_crow[r] = sd[0];
}

// ---------------------------------------------------------------------------
// Gather precomputed P = codebook @ proj_out_w + b, apply repeat/mask/pos.
// ---------------------------------------------------------------------------
__global__ void gather_k(const float* __restrict__ P,
                         const float* __restrict__ pos,
                         float* __restrict__ out) {
    int i = blockIdx.x * blockDim.x + threadIdx.x;
    if (i >= MROWS * (DD / 4)) return;
    int d4 = i & (DD / 4 - 1);
    int bt = i >> 7;
    int b = bt / TT, t = bt % TT;
    int sel = g_mask[bt] ? g_idx[b * TSD + (t >> 1)] : (CBN - 1);
    float4 pv = ((const float4*)(P   + (size_t)sel * DD))[d4];
    float4 ev = ((const float4*)(pos + (size_t)t   * DD))[d4];
    float4 r;
    r.x = pv.x + ev.x;  r.y = pv.y + ev.y;
    r.z = pv.z + ev.z;  r.w = pv.w + ev.w;
    ((float4*)(out + (size_t)bt * DD))[d4] = r;
}

// ---------------------------------------------------------------------------
// Flash attention over the packed QKV buffer [MROWS, 1536].
// ---------------------------------------------------------------------------
#define AQB 128

__global__ __launch_bounds__(AQB)
void attn_k(const float* __restrict__ QKV, float* __restrict__ O) {
    __shared__ float Ks[64][HDD];
    __shared__ float Vs[64][HDD];
    __shared__ float Ss[32][AQB];

    int h = blockIdx.y, b = blockIdx.z;
    int tid = threadIdx.x;
    int qi = blockIdx.x * AQB + tid;
    bool valid = qi < TT;

    float q[HDD];
    if (valid) {
        const float4* qp = (const float4*)(QKV + ((size_t)(b * TT + qi)) * QKVW
                                               + h * HDD);
        #pragma unroll
        for (int d4 = 0; d4 < HDD / 4; d4++) {
            float4 v = qp[d4];
            q[d4 * 4 + 0] = v.x; q[d4 * 4 + 1] = v.y;
            q[d4 * 4 + 2] = v.z; q[d4 * 4 + 3] = v.w;
        }
    }

    float m = -1e30f, l = 0.f;
    float o[HDD];
    #pragma unroll
    for (int d = 0; d < HDD; d++) o[d] = 0.f;

    const float4 z4 = make_float4(0.f, 0.f, 0.f, 0.f);

    for (int kb = 0; kb < TT; kb += 64) {
        #pragma unroll
        for (int i = 0; i < 8; i++) {
            int e   = tid + i * AQB;
            int row = e >> 4;
            int c4  = (e & 15) * 4;
            int kt  = kb + row;
            float4 kv = z4, vv = z4;
            if (kt < TT) {
                size_t base = ((size_t)(b * TT + kt)) * QKVW + h * HDD + c4;
                kv = *(const float4*)(QKV + base + DD);
                vv = *(const float4*)(QKV + base + 2 * DD);
            }
            *(float4*)&Ks[row][c4] = kv;
            *(float4*)&Vs[row][c4] = vv;
        }
        __syncthreads();

        int nk = min(64, TT - kb);
        if (valid) {
            #pragma unroll
            for (int c = 0; c < 2; c++) {
                int jb = c * 32;
                if (jb >= nk) break;
                int jn = min(32, nk - jb);

                float tm = -1e30f;
                for (int j = 0; j < jn; j++) {
                    float s = 0.f;
                    #pragma unroll
                    for (int d = 0; d < HDD; d++) s += q[d] * Ks[jb + j][d];
                    Ss[j][tid] = s;
                    tm = fmaxf(tm, s);
                }

                float nm = fmaxf(m, tm);
                float sc = __expf(m - nm);
                l *= sc;
                #pragma unroll
                for (int d = 0; d < HDD; d++) o[d] *= sc;

                for (int j = 0; j < jn; j++) {
                    float p = __expf(Ss[j][tid] - nm);
                    l += p;
                    #pragma unroll
                    for (int d = 0; d < HDD; d++) o[d] += p * Vs[jb + j][d];
                }
                m = nm;
            }
        }
        __syncthreads();
    }

    if (valid) {
        float invl = 1.0f / l;
        float4* op = (float4*)(O + ((size_t)(b * TT + qi)) * DD + h * HDD);
        #pragma unroll
        for (int d4 = 0; d4 < HDD / 4; d4++) {
            float4 v;
            v.x = o[d4 * 4 + 0] * invl;
            v.y = o[d4 * 4 + 1] * invl;
            v.z = o[d4 * 4 + 2] * invl;
            v.w = o[d4 * 4 + 3] * invl;
            op[d4] = v;
        }
    }
}

// ---------------------------------------------------------------------------
// Deterministic commit-loss reduction.
// ---------------------------------------------------------------------------
__global__ __launch_bounds__(256)
void fin_k(float* __restrict__ out, int pos) {
    __shared__ float red[256];
    int tid = threadIdx.x;
    float s = 0.f;
    for (int r = tid; r < MROWS_DS; r += 256) s += g_crow[r];
    red[tid] = s;
    __syncthreads();
    for (int o = 128; o > 0; o >>= 1) {
        if (tid < o) red[tid] += red[tid + o];
        __syncthreads();
    }
    if (tid == 0) out[pos] = red[0] * (1.0f / (float)COMMIT_N);
}

// ---------------------------------------------------------------------------
// Launch
// ---------------------------------------------------------------------------
static float* sym(const void* s) {
    void* p = nullptr;
    cudaGetSymbolAddress(&p, s);
    return (float*)p;
}

extern "C" void kernel_launch(void* const* d_in, const int* in_sizes, int n_in,
                              void* d_out, int out_size) {
    const float* embs      = (const float*)d_in[0];
    const void*  maskraw   = d_in[1];
    const float* mlp_ln_g  = (const float*)d_in[2];
    const float* mlp_ln_b  = (const float*)d_in[3];
    const float* mlp_w1    = (const float*)d_in[4];
    const float* mlp_b1    = (const float*)d_in[5];
    const float* mlp_w2    = (const float*)d_in[6];
    const float* mlp_b2    = (const float*)d_in[7];
    const float* proj_in_w = (const float*)d_in[8];
    const float* proj_in_b = (const float*)d_in[9];
    const float* codebook  = (const float*)d_in[10];
    const float* proj_out_w= (const float*)d_in[11];
    const float* proj_out_b= (const float*)d_in[12];
    const float* pos_emb   = (const float*)d_in[13];
    const float* attn_ln_g = (const float*)d_in[14];
    const float* attn_ln_b = (const float*)d_in[15];
    const float* wq        = (const float*)d_in[16];
    const float* bq        = (const float*)d_in[17];
    const float* wk        = (const float*)d_in[18];
    const float* bk        = (const float*)d_in[19];
    const float* wv        = (const float*)d_in[20];
    const float* bv        = (const float*)d_in[21];
    const float* wo        = (const float*)d_in[22];
    const float* bo        = (const float*)d_in[23];
    const float* ffn_ln_g  = (const float*)d_in[24];
    const float* ffn_ln_b  = (const float*)d_in[25];
    const float* ffn_w1    = (const float*)d_in[26];
    const float* ffn_b1    = (const float*)d_in[27];
    const float* ffn_w2    = (const float*)d_in[28];
    const float* ffn_b2    = (const float*)d_in[29];
    const float* ln_post_g = (const float*)d_in[30];
    const float* ln_post_b = (const float*)d_in[31];

    float* out = (float*)d_out;

    float* px     = sym(g_x);
    float* pln    = sym(g_ln);
    float* pff    = sym(g_ff);
    float* pxq    = sym(g_xq);
    float* ppcb   = sym(g_pcb);
    float* pxfull = sym(g_xfull);
    float* pwqkv  = sym(g_wqkv);
    float* pbqkv  = sym(g_bqkv);
    float* pqkv   = sym(g_qkv);
    float* po     = sym(g_ob);

    maskdetect_k<<<1, 256>>>((const unsigned int*)maskraw);
    maskconv_k<<<(MROWS + 255) / 256, 256>>>(maskraw);

    // x = embs[:, ::2]
    ds_k<<<(MROWS_DS * (DD / 4) + 255) / 256, 256>>>(embs, px);

    // pack QKV weights; codebook norms + precomputed proj_out of codebook
    qkvcat_k<<<(DD * DD + 255) / 256, 256>>>(wq, wk, wv, bq, bk, bv);
    cbn_k<<<(CBN + 255) / 256, 256>>>(codebook);
    {
        dim3 g((DD + BN - 1) / BN, (CBN + BM - 1) / BM);
        sgemm_k<false, false><<<g, 256>>>(codebook, proj_out_w, proj_out_b,
                                          nullptr, ppcb, CBN, DD, CDD);
    }

    // MLP block (fp32 — upstream of VQ argmin, must stay exact)
    ln_k<<<MROWS_DS, 256>>>(px, pln, mlp_ln_g, mlp_ln_b);
    {
        dim3 g1((FFD + BN - 1) / BN, (MROWS_DS + BM - 1) / BM);
        sgemm_k<true, false><<<g1, 256>>>(pln, mlp_w1, mlp_b1, nullptr, pff,
                                          MROWS_DS, FFD, DD);
        dim3 g2((DD + BN - 1) / BN, (MROWS_DS + BM - 1) / BM);
        sgemm_k<false, true><<<g2, 256>>>(pff, mlp_w2, mlp_b2, px, px,
                                          MROWS_DS, DD, FFD);
    }

    // proj_in (fp32 — upstream of VQ argmin)
    {
        dim3 g((CDD + BN - 1) / BN, (MROWS_DS + BM - 1) / BM);
        sgemm_k<false, false><<<g, 256>>>(px, proj_in_w, proj_in_b, nullptr, pxq,
                                          MROWS_DS, CDD, DD);
    }

    // VQ
    vq_k<<<MROWS_DS, 128>>>(pxq, codebook);

    // gather P[sel] + pos_emb  (repeat + mask fused)
    gather_k<<<(MROWS * (DD / 4) + 255) / 256, 256>>>(ppcb, pos_emb, pxfull);

    // Attention block (tf32 tensor cores downstream of argmin)
    ln_k<<<MROWS, 256>>>(pxfull, pln, attn_ln_g, attn_ln_b);
    {
        dim3 g(QKVW / BN, (MROWS + BM - 1) / BM);
        tgemm_k<false, false><<<g, 256>>>(pln, pwqkv, pbqkv, nullptr, pqkv,
                                          MROWS, QKVW, DD);
    }
    {
        dim3 g((TT + AQB - 1) / AQB, HH, BB);
        attn_k<<<g, AQB>>>(pqkv, po);
    }
    {
        dim3 g(DD / BN, (MROWS + BM - 1) / BM);
        tgemm_k<false, true><<<g, 256>>>(po, wo, bo, pxfull, pxfull, MROWS, DD, DD);
    }

    // FFN block (tf32)
    ln_k<<<MROWS, 256>>>(pxfull, pln, ffn_ln_g, ffn_ln_b);
    {
        dim3 g1(FFD / BN, (MROWS + BM - 1) / BM);
        tgemm_k<true, false><<<g1, 256>>>(pln, ffn_w1, ffn_b1, nullptr, pff,
                                          MROWS, FFD, DD);
        dim3 g2(DD / BN, (MROWS + BM - 1) / BM);
        tgemm_k<false, true><<<g2, 256>>>(pff, ffn_w2, ffn_b2, pxfull, pxfull,
                                          MROWS, DD, FFD);
    }

    // final LN straight into d_out; commit loss in the last slot
    ln_k<<<MROWS, 256>>>(pxfull, out, ln_post_g, ln_post_b);
    fin_k<<<1, 256>>>(out, out_size - 1);
}